// round 5
// baseline (speedup 1.0000x reference)
#include <cuda_runtime.h>

#define BB 4
#define NN 8192
#define DD 16
#define RR 32
#define HH 64
#define EE 262144

typedef unsigned long long u64;

// ---- f32x2 packed-math helpers (full fp32 precision, 2x FFMA pipe tput) ----
__device__ __forceinline__ u64 pk2(float x, float y) {
    u64 r; asm("mov.b64 %0, {%1, %2};" : "=l"(r) : "f"(x), "f"(y)); return r;
}
__device__ __forceinline__ void up2(u64 v, float& x, float& y) {
    asm("mov.b64 {%0, %1}, %2;" : "=f"(x), "=f"(y) : "l"(v));
}
__device__ __forceinline__ void fma2(u64& d, u64 a, u64 b) {
    asm("fma.rn.f32x2 %0, %1, %2, %3;" : "=l"(d) : "l"(a), "l"(b), "l"(d));
}
__device__ __forceinline__ void add2(u64& d, u64 a) {
    asm("add.rn.f32x2 %0, %1, %2;" : "=l"(d) : "l"(d), "l"(a));
}

// Scratch (allocation-free: __device__ globals)
__device__ float g_P1[BB * NN * HH];   // particles @ W1[:16] + b1
__device__ float g_P2[BB * NN * HH];   // particles @ W1[16:]
__device__ float g_rel[BB * NN * RR];  // scatter-add target

// ---------------------------------------------------------------------------
// Kernel A: per-node first-layer projections + zero the rel buffer.
// 4 threads per (b,n): each covers 16 output columns of P1 and P2.
// grid = 512 blocks (was 128 -> occupancy fix), f32x2 math.
// ---------------------------------------------------------------------------
__global__ __launch_bounds__(256) void node_proj_kernel(
    const float* __restrict__ particles,
    const float* __restrict__ W1,   // [32, 64] row-major
    const float* __restrict__ b1)   // [64]
{
    __shared__ float sW1[32 * 64];
    __shared__ float sb1[64];
    for (int i = threadIdx.x; i < 32 * 64; i += 256) sW1[i] = W1[i];
    if (threadIdx.x < 64) sb1[threadIdx.x] = b1[threadIdx.x];
    __syncthreads();

    int gid  = blockIdx.x * 256 + threadIdx.x;  // 0 .. B*N*4-1
    int node = gid >> 2;
    int cg   = gid & 3;
    int c0   = cg * 16;                         // column offset

    float x[16];
    const float4* xp = (const float4*)(particles + (size_t)node * 16);
    #pragma unroll
    for (int c = 0; c < 4; c++) {
        float4 v = xp[c];
        x[4*c+0] = v.x; x[4*c+1] = v.y; x[4*c+2] = v.z; x[4*c+3] = v.w;
    }

    u64 a1[8], a2[8];
    const u64* bp = (const u64*)&sb1[c0];
    #pragma unroll
    for (int p = 0; p < 8; p++) { a1[p] = bp[p]; a2[p] = 0ull; }

    #pragma unroll
    for (int i = 0; i < 16; i++) {
        u64 xv = pk2(x[i], x[i]);
        const u64* w1p = (const u64*)&sW1[i * 64 + c0];
        const u64* w2p = (const u64*)&sW1[(16 + i) * 64 + c0];
        #pragma unroll
        for (int p = 0; p < 8; p++) fma2(a1[p], xv, w1p[p]);
        #pragma unroll
        for (int p = 0; p < 8; p++) fma2(a2[p], xv, w2p[p]);
    }

    u64* o1 = (u64*)(g_P1 + (size_t)node * 64 + c0);
    u64* o2 = (u64*)(g_P2 + (size_t)node * 64 + c0);
    #pragma unroll
    for (int p = 0; p < 8; p++) { o1[p] = a1[p]; o2[p] = a2[p]; }

    // zero this thread's slice of rel
    float4* relo = (float4*)(g_rel + (size_t)node * 32 + cg * 8);
    relo[0] = make_float4(0.f, 0.f, 0.f, 0.f);
    relo[1] = make_float4(0.f, 0.f, 0.f, 0.f);
}

// ---------------------------------------------------------------------------
// Kernel B: edge MLP (dominant). Tiled GEMM formulation:
//   block = 512 edges x 32 outputs (one batch), K=64 in chunks of 16.
//   h = relu(P1[s] + P2[r]) staged TRANSPOSED in shared (shH[k][edge]),
//   W2 chunk in shared; each thread computes 8 edges x 8 outputs with
//   f32x2 FMAs (32 fma2 per k per thread, 4 LDS.128 per k).
//   Epilogue: relu + red.global.add.v4.f32 scatter.
// ---------------------------------------------------------------------------
__global__ __launch_bounds__(256, 2) void edge_kernel(
    const int* __restrict__ senders,
    const int* __restrict__ receivers,
    const float* __restrict__ W2,   // [64, 32] row-major
    const float* __restrict__ b2)   // [32]
{
    __shared__ int   sS[512], sR[512];
    __shared__ float shH[16][512];   // h chunk, transposed
    __shared__ float sW[16][32];     // W2 chunk

    int tid  = threadIdx.x;
    int base = blockIdx.x * 512;
    int b    = blockIdx.y;

    sS[tid]       = senders[base + tid];
    sR[tid]       = receivers[base + tid];
    sS[tid + 256] = senders[base + tid + 256];
    sR[tid + 256] = receivers[base + tid + 256];

    int row = tid >> 2;          // 0..63
    int j0  = (tid & 3) * 8;     // 0,8,16,24
    int er0 = row * 8;           // first edge of this thread's 8

    // acc init from b2 (pairs)
    u64 acc[8][4];
    {
        float4 bv0 = *(const float4*)(b2 + j0);
        float4 bv1 = *(const float4*)(b2 + j0 + 4);
        u64 bi0 = pk2(bv0.x, bv0.y), bi1 = pk2(bv0.z, bv0.w);
        u64 bi2 = pk2(bv1.x, bv1.y), bi3 = pk2(bv1.z, bv1.w);
        #pragma unroll
        for (int e = 0; e < 8; e++) {
            acc[e][0] = bi0; acc[e][1] = bi1; acc[e][2] = bi2; acc[e][3] = bi3;
        }
    }
    __syncthreads();  // sS/sR visible

    const float* P1b = g_P1 + (size_t)b * NN * 64;
    const float* P2b = g_P2 + (size_t)b * NN * 64;

    #pragma unroll 1
    for (int ch = 0; ch < 4; ch++) {
        // stage W2 chunk: 16 rows x 32 cols = 512 floats
        ((float*)sW)[tid]       = W2[ch * 512 + tid];
        ((float*)sW)[tid + 256] = W2[ch * 512 + tid + 256];

        // stage h chunk for edges tid and tid+256 (conflict-free STS: lane==edge%32... wait lane writes column e=tid)
        #pragma unroll
        for (int t2 = 0; t2 < 2; t2++) {
            int e = tid + t2 * 256;
            int s = sS[e], r = sR[e];
            const float4* p1 = (const float4*)(P1b + s * 64 + ch * 16);
            const float4* p2 = (const float4*)(P2b + r * 64 + ch * 16);
            #pragma unroll
            for (int q = 0; q < 4; q++) {
                float4 a = p1[q], c = p2[q];
                shH[q * 4 + 0][e] = fmaxf(a.x + c.x, 0.f);
                shH[q * 4 + 1][e] = fmaxf(a.y + c.y, 0.f);
                shH[q * 4 + 2][e] = fmaxf(a.z + c.z, 0.f);
                shH[q * 4 + 3][e] = fmaxf(a.w + c.w, 0.f);
            }
        }
        __syncthreads();

        #pragma unroll
        for (int k = 0; k < 16; k++) {
            float4 ha = *(const float4*)&shH[k][er0];
            float4 hb = *(const float4*)&shH[k][er0 + 4];
            ulonglong2 wa = *(const ulonglong2*)&sW[k][j0];
            ulonglong2 wb = *(const ulonglong2*)&sW[k][j0 + 4];
            u64 w0 = wa.x, w1 = wa.y, w2v = wb.x, w3 = wb.y;
            float hv[8] = {ha.x, ha.y, ha.z, ha.w, hb.x, hb.y, hb.z, hb.w};
            #pragma unroll
            for (int e = 0; e < 8; e++) {
                u64 hp = pk2(hv[e], hv[e]);
                fma2(acc[e][0], hp, w0);
                fma2(acc[e][1], hp, w1);
                fma2(acc[e][2], hp, w2v);
                fma2(acc[e][3], hp, w3);
            }
        }
        __syncthreads();
    }

    // epilogue: relu + vector atomic scatter
    float* relb = g_rel + (size_t)b * NN * 32;
    #pragma unroll
    for (int e = 0; e < 8; e++) {
        int r = sR[er0 + e];
        float f[8];
        up2(acc[e][0], f[0], f[1]); up2(acc[e][1], f[2], f[3]);
        up2(acc[e][2], f[4], f[5]); up2(acc[e][3], f[6], f[7]);
        #pragma unroll
        for (int q = 0; q < 8; q++) f[q] = fmaxf(f[q], 0.f);
        float* ptr = relb + (size_t)r * 32 + j0;
        asm volatile("red.global.add.v4.f32 [%0], {%1, %2, %3, %4};"
                     :: "l"(ptr), "f"(f[0]), "f"(f[1]), "f"(f[2]), "f"(f[3]) : "memory");
        asm volatile("red.global.add.v4.f32 [%0], {%1, %2, %3, %4};"
                     :: "l"(ptr + 4), "f"(f[4]), "f"(f[5]), "f"(f[6]), "f"(f[7]) : "memory");
    }
}

// ---------------------------------------------------------------------------
// Kernel C: node MLP + residual. 2 threads per (b,n): each computes half of
// the 64 hidden units and a partial delta[16]; partials combined via shared.
// grid = 256 blocks, f32x2 math.
// ---------------------------------------------------------------------------
__global__ __launch_bounds__(256) void node_out_kernel(
    const float* __restrict__ particles,
    const float* __restrict__ W3,   // [48, 64]
    const float* __restrict__ b3,   // [64]
    const float* __restrict__ W4,   // [64, 16]
    const float* __restrict__ b4,   // [16]
    float* __restrict__ out)
{
    __shared__ float sW3[48 * 64];
    __shared__ float sW4[64 * 16];
    __shared__ float sb3[64];
    __shared__ u64   sPart[256][9];   // padded to dodge bank conflicts
    for (int i = threadIdx.x; i < 48 * 64; i += 256) sW3[i] = W3[i];
    for (int i = threadIdx.x; i < 64 * 16; i += 256) sW4[i] = W4[i];
    if (threadIdx.x < 64) sb3[threadIdx.x] = b3[threadIdx.x];
    __syncthreads();

    int gid  = blockIdx.x * 256 + threadIdx.x;
    int node = gid >> 1;
    int half = gid & 1;
    int h0   = half * 32;

    float x[48];
    const float4* pp = (const float4*)(particles + (size_t)node * 16);
    #pragma unroll
    for (int c = 0; c < 4; c++) {
        float4 v = pp[c];
        x[4*c+0] = v.x; x[4*c+1] = v.y; x[4*c+2] = v.z; x[4*c+3] = v.w;
    }
    const float4* rp = (const float4*)(g_rel + (size_t)node * 32);
    #pragma unroll
    for (int c = 0; c < 8; c++) {
        float4 v = rp[c];
        x[16+4*c+0] = v.x; x[16+4*c+1] = v.y; x[16+4*c+2] = v.z; x[16+4*c+3] = v.w;
    }

    // hidden half: 32 units as 16 f32x2 pairs
    u64 t[16];
    const u64* b3p = (const u64*)&sb3[h0];
    #pragma unroll
    for (int p = 0; p < 16; p++) t[p] = b3p[p];

    #pragma unroll
    for (int i = 0; i < 48; i++) {
        u64 xv = pk2(x[i], x[i]);
        const u64* wp = (const u64*)&sW3[i * 64 + h0];
        #pragma unroll
        for (int p = 0; p < 16; p++) fma2(t[p], xv, wp[p]);
    }
    float ts[32];
    #pragma unroll
    for (int p = 0; p < 16; p++) {
        float u, v; up2(t[p], u, v);
        ts[2*p]   = fmaxf(u, 0.f);
        ts[2*p+1] = fmaxf(v, 0.f);
    }

    // partial delta[16] as 8 pairs (half 0 carries the bias)
    u64 d[8];
    if (half == 0) {
        const u64* b4p = (const u64*)b4;
        #pragma unroll
        for (int p = 0; p < 8; p++) d[p] = b4p[p];
    } else {
        #pragma unroll
        for (int p = 0; p < 8; p++) d[p] = 0ull;
    }
    #pragma unroll
    for (int i = 0; i < 32; i++) {
        u64 tv = pk2(ts[i], ts[i]);
        const u64* wp = (const u64*)&sW4[(h0 + i) * 16];
        #pragma unroll
        for (int p = 0; p < 8; p++) fma2(d[p], tv, wp[p]);
    }

    #pragma unroll
    for (int p = 0; p < 8; p++) sPart[threadIdx.x][p] = d[p];
    __syncthreads();

    if (half == 0) {
        #pragma unroll
        for (int p = 0; p < 8; p++) add2(d[p], sPart[threadIdx.x + 1][p]);
        float4* outp = (float4*)(out + (size_t)node * 16);
        #pragma unroll
        for (int c = 0; c < 4; c++) {
            float d0, d1, d2, d3;
            up2(d[2*c], d0, d1); up2(d[2*c+1], d2, d3);
            outp[c] = make_float4(x[4*c+0] + d0, x[4*c+1] + d1,
                                  x[4*c+2] + d2, x[4*c+3] + d3);
        }
    }
}

extern "C" void kernel_launch(void* const* d_in, const int* in_sizes, int n_in,
                              void* d_out, int out_size)
{
    const float* particles = (const float*)d_in[0];
    const int*   senders   = (const int*)d_in[1];
    const int*   receivers = (const int*)d_in[2];
    const float* W1 = (const float*)d_in[3];
    const float* b1 = (const float*)d_in[4];
    const float* W2 = (const float*)d_in[5];
    const float* b2 = (const float*)d_in[6];
    const float* W3 = (const float*)d_in[7];
    const float* b3 = (const float*)d_in[8];
    const float* W4 = (const float*)d_in[9];
    const float* b4 = (const float*)d_in[10];
    float* out = (float*)d_out;

    node_proj_kernel<<<(BB * NN * 4) / 256, 256>>>(particles, W1, b1);

    dim3 egrid(EE / 512, BB);
    edge_kernel<<<egrid, 256>>>(senders, receivers, W2, b2);

    node_out_kernel<<<(BB * NN * 2) / 256, 256>>>(particles, W3, b3, W4, b4, out);
}

// round 7
// speedup vs baseline: 2.0992x; 2.0992x over previous
#include <cuda_runtime.h>

#define BB 4
#define NN 8192
#define DD 16
#define RR 32
#define HH 64
#define EE 262144

typedef unsigned long long u64;

// ---- f32x2 packed-math helpers (full fp32 precision, 2x FFMA pipe tput) ----
__device__ __forceinline__ u64 pk2(float x, float y) {
    u64 r; asm("mov.b64 %0, {%1, %2};" : "=l"(r) : "f"(x), "f"(y)); return r;
}
__device__ __forceinline__ void up2(u64 v, float& x, float& y) {
    asm("mov.b64 {%0, %1}, %2;" : "=f"(x), "=f"(y) : "l"(v));
}
__device__ __forceinline__ void fma2(u64& d, u64 a, u64 b) {
    asm("fma.rn.f32x2 %0, %1, %2, %3;" : "=l"(d) : "l"(a), "l"(b), "l"(d));
}

// Scratch (allocation-free: __device__ globals)
__device__ float g_P1[BB * NN * HH];   // particles @ W1[:16] + b1
__device__ float g_P2[BB * NN * HH];   // particles @ W1[16:]
__device__ float g_rel[BB * NN * RR];  // scatter-add target

// ---------------------------------------------------------------------------
// Kernel A (R3-proven version): per-node first-layer projections + zero rel.
// One thread per (b, n).
// ---------------------------------------------------------------------------
__global__ __launch_bounds__(256) void node_proj_kernel(
    const float* __restrict__ particles,
    const float* __restrict__ W1,   // [32, 64] row-major
    const float* __restrict__ b1)   // [64]
{
    __shared__ float sW1[32 * 64];
    __shared__ float sb1[64];
    for (int i = threadIdx.x; i < 32 * 64; i += 256) sW1[i] = W1[i];
    if (threadIdx.x < 64) sb1[threadIdx.x] = b1[threadIdx.x];
    __syncthreads();

    int idx = blockIdx.x * 256 + threadIdx.x;  // 0 .. B*N-1

    float x[16];
    const float4* xp = (const float4*)(particles + (size_t)idx * 16);
    #pragma unroll
    for (int c = 0; c < 4; c++) {
        float4 v = xp[c];
        x[4 * c + 0] = v.x; x[4 * c + 1] = v.y; x[4 * c + 2] = v.z; x[4 * c + 3] = v.w;
    }

    float4* P1o = (float4*)(g_P1 + (size_t)idx * 64);
    float4* P2o = (float4*)(g_P2 + (size_t)idx * 64);

    #pragma unroll
    for (int c = 0; c < 16; c++) {
        float4 acc = ((const float4*)sb1)[c];
        #pragma unroll
        for (int i = 0; i < 16; i++) {
            float4 w = ((const float4*)(sW1 + i * 64))[c];
            acc.x += x[i] * w.x; acc.y += x[i] * w.y;
            acc.z += x[i] * w.z; acc.w += x[i] * w.w;
        }
        P1o[c] = acc;
    }
    #pragma unroll
    for (int c = 0; c < 16; c++) {
        float4 acc = make_float4(0.f, 0.f, 0.f, 0.f);
        #pragma unroll
        for (int i = 0; i < 16; i++) {
            float4 w = ((const float4*)(sW1 + (16 + i) * 64))[c];
            acc.x += x[i] * w.x; acc.y += x[i] * w.y;
            acc.z += x[i] * w.z; acc.w += x[i] * w.w;
        }
        P2o[c] = acc;
    }

    float4* relo = (float4*)(g_rel + (size_t)idx * 32);
    #pragma unroll
    for (int c = 0; c < 8; c++) relo[c] = make_float4(0.f, 0.f, 0.f, 0.f);
}

// ---------------------------------------------------------------------------
// Kernel B: edge MLP. Block = 256 edges (one batch).
// Phase structure per 32-k chunk:
//   gather: warp w owns edges [w*32, w*32+32). One warp inst fetches float4s
//           of P1[s] (lanes side=0) and P2[r] (lanes side=1) for 2 edges
//           -> 4 cache lines / inst instead of 32. shfl_xor(8) combines,
//           relu, stage h edge-major: shH[e*33 + k] (pad 33: conflict-free).
//   mma:    thread = (jg = tid>>6, eg = tid&63); 4 strided edges {eg+64i},
//           8 output cols; weights broadcast from smem as u64 pairs; f32x2.
// Epilogue: relu + red.global.add.v4.f32 scatter.
// ---------------------------------------------------------------------------
__global__ __launch_bounds__(256) void edge_kernel(
    const int* __restrict__ senders,
    const int* __restrict__ receivers,
    const float* __restrict__ W2,   // [64, 32] row-major
    const float* __restrict__ b2)   // [32]
{
    __shared__ float shH[256 * 33];   // h chunk, edge-major, padded
    __shared__ float sW[64 * 32];
    __shared__ float sb2v[32];
    __shared__ int   sS[256], sR[256];

    int tid  = threadIdx.x;
    int base = blockIdx.x * 256;
    int b    = blockIdx.y;

    sS[tid] = senders[base + tid];
    sR[tid] = receivers[base + tid];
    for (int i = tid; i < 64 * 32; i += 256) sW[i] = W2[i];
    if (tid < 32) sb2v[tid] = b2[tid];
    __syncthreads();

    const float* P1b = g_P1 + (size_t)b * NN * 64;
    const float* P2b = g_P2 + (size_t)b * NN * 64;

    int lane = tid & 31;
    int w    = tid >> 5;            // warp id 0..7 (gather: edges w*32..+31)
    int half = (lane >> 4) & 1;     // which of the 2 edges in this inst
    int side = (lane >> 3) & 1;     // 0 = P1[sender], 1 = P2[receiver]
    int c    = lane & 7;            // float4 chunk (covers k = 4c..4c+3)

    int jg = tid >> 6;              // 0..3 (constant within a warp)
    int eg = tid & 63;              // edges eg + 64*i
    int j0 = jg * 8;

    // accumulators: 4 edges x 8 cols as u64 pairs, init from b2
    u64 acc[4][4];
    {
        const u64* bp = (const u64*)&sb2v[j0];
        u64 b0 = bp[0], b1v = bp[1], b2v_ = bp[2], b3v = bp[3];
        #pragma unroll
        for (int i = 0; i < 4; i++) {
            acc[i][0] = b0; acc[i][1] = b1v; acc[i][2] = b2v_; acc[i][3] = b3v;
        }
    }

    const float* myP = side ? P2b : P1b;

    #pragma unroll 1
    for (int ch = 0; ch < 2; ch++) {
        // ---------------- gather phase (16 iters, unrolled x4 for MLP) ----
        #pragma unroll 1
        for (int it = 0; it < 16; it += 4) {
            float4 v[4];
            int    e[4];
            #pragma unroll
            for (int u = 0; u < 4; u++) {
                e[u] = w * 32 + (it + u) * 2 + half;
                int node = side ? sR[e[u]] : sS[e[u]];
                v[u] = *((const float4*)(myP + (size_t)node * 64) + ch * 8 + c);
            }
            #pragma unroll
            for (int u = 0; u < 4; u++) {
                float4 o;
                o.x = v[u].x + __shfl_xor_sync(0xffffffffu, v[u].x, 8);
                o.y = v[u].y + __shfl_xor_sync(0xffffffffu, v[u].y, 8);
                o.z = v[u].z + __shfl_xor_sync(0xffffffffu, v[u].z, 8);
                o.w = v[u].w + __shfl_xor_sync(0xffffffffu, v[u].w, 8);
                if (side == 0) {
                    float* dst = &shH[e[u] * 33 + 4 * c];
                    dst[0] = fmaxf(o.x, 0.f);
                    dst[1] = fmaxf(o.y, 0.f);
                    dst[2] = fmaxf(o.z, 0.f);
                    dst[3] = fmaxf(o.w, 0.f);
                }
            }
        }
        __syncthreads();

        // ---------------- mma phase over k in [ch*32, ch*32+32) -----------
        #pragma unroll 4
        for (int kk = 0; kk < 32; kk++) {
            int k = ch * 32 + kk;
            const ulonglong2* wp = (const ulonglong2*)&sW[k * 32 + j0];
            ulonglong2 wa = wp[0];
            ulonglong2 wb = wp[1];
            #pragma unroll
            for (int i = 0; i < 4; i++) {
                float hv = shH[(eg + 64 * i) * 33 + kk];
                u64 hp = pk2(hv, hv);
                fma2(acc[i][0], hp, wa.x);
                fma2(acc[i][1], hp, wa.y);
                fma2(acc[i][2], hp, wb.x);
                fma2(acc[i][3], hp, wb.y);
            }
        }
        __syncthreads();
    }

    // ---------------- epilogue: relu + vector atomic scatter --------------
    float* relb = g_rel + (size_t)b * NN * 32;
    #pragma unroll
    for (int i = 0; i < 4; i++) {
        int e = eg + 64 * i;
        int r = sR[e];
        float f[8];
        up2(acc[i][0], f[0], f[1]); up2(acc[i][1], f[2], f[3]);
        up2(acc[i][2], f[4], f[5]); up2(acc[i][3], f[6], f[7]);
        #pragma unroll
        for (int q = 0; q < 8; q++) f[q] = fmaxf(f[q], 0.f);
        float* ptr = relb + (size_t)r * 32 + j0;
        asm volatile("red.global.add.v4.f32 [%0], {%1, %2, %3, %4};"
                     :: "l"(ptr), "f"(f[0]), "f"(f[1]), "f"(f[2]), "f"(f[3]) : "memory");
        asm volatile("red.global.add.v4.f32 [%0], {%1, %2, %3, %4};"
                     :: "l"(ptr + 4), "f"(f[4]), "f"(f[5]), "f"(f[6]), "f"(f[7]) : "memory");
    }
}

// ---------------------------------------------------------------------------
// Kernel C (R3-proven version): node MLP + residual. One thread per (b, n).
// ---------------------------------------------------------------------------
__global__ __launch_bounds__(256) void node_out_kernel(
    const float* __restrict__ particles,
    const float* __restrict__ W3,   // [48, 64]
    const float* __restrict__ b3,   // [64]
    const float* __restrict__ W4,   // [64, 16]
    const float* __restrict__ b4,   // [16]
    float* __restrict__ out)
{
    __shared__ float sW3[48 * 64];
    __shared__ float sW4[64 * 16];
    __shared__ float sb3[64];
    __shared__ float sb4[16];
    for (int i = threadIdx.x; i < 48 * 64; i += 256) sW3[i] = W3[i];
    for (int i = threadIdx.x; i < 64 * 16; i += 256) sW4[i] = W4[i];
    if (threadIdx.x < 64) sb3[threadIdx.x] = b3[threadIdx.x];
    if (threadIdx.x < 16) sb4[threadIdx.x] = b4[threadIdx.x];
    __syncthreads();

    int idx = blockIdx.x * 256 + threadIdx.x;

    float x[48];
    const float4* pp = (const float4*)(particles + (size_t)idx * 16);
    #pragma unroll
    for (int c = 0; c < 4; c++) {
        float4 v = pp[c];
        x[4 * c + 0] = v.x; x[4 * c + 1] = v.y; x[4 * c + 2] = v.z; x[4 * c + 3] = v.w;
    }
    const float4* rp = (const float4*)(g_rel + (size_t)idx * 32);
    #pragma unroll
    for (int c = 0; c < 8; c++) {
        float4 v = rp[c];
        x[16 + 4 * c + 0] = v.x; x[16 + 4 * c + 1] = v.y;
        x[16 + 4 * c + 2] = v.z; x[16 + 4 * c + 3] = v.w;
    }

    float delta[16];
    #pragma unroll
    for (int j = 0; j < 16; j++) delta[j] = sb4[j];

    #pragma unroll
    for (int half = 0; half < 2; half++) {
        float t[32];
        #pragma unroll
        for (int j = 0; j < 32; j++) t[j] = sb3[half * 32 + j];

        #pragma unroll
        for (int i = 0; i < 48; i++) {
            const float4* w = (const float4*)(sW3 + i * 64 + half * 32);
            float xv = x[i];
            #pragma unroll
            for (int j = 0; j < 8; j++) {
                float4 wv = w[j];
                t[4 * j + 0] += xv * wv.x;
                t[4 * j + 1] += xv * wv.y;
                t[4 * j + 2] += xv * wv.z;
                t[4 * j + 3] += xv * wv.w;
            }
        }
        #pragma unroll
        for (int j = 0; j < 32; j++) t[j] = fmaxf(t[j], 0.f);

        #pragma unroll
        for (int i = 0; i < 32; i++) {
            const float4* w = (const float4*)(sW4 + (half * 32 + i) * 16);
            float tv = t[i];
            #pragma unroll
            for (int j = 0; j < 4; j++) {
                float4 wv = w[j];
                delta[4 * j + 0] += tv * wv.x;
                delta[4 * j + 1] += tv * wv.y;
                delta[4 * j + 2] += tv * wv.z;
                delta[4 * j + 3] += tv * wv.w;
            }
        }
    }

    float4* outp = (float4*)(out + (size_t)idx * 16);
    #pragma unroll
    for (int c = 0; c < 4; c++) {
        outp[c] = make_float4(x[4 * c + 0] + delta[4 * c + 0],
                              x[4 * c + 1] + delta[4 * c + 1],
                              x[4 * c + 2] + delta[4 * c + 2],
                              x[4 * c + 3] + delta[4 * c + 3]);
    }
}

extern "C" void kernel_launch(void* const* d_in, const int* in_sizes, int n_in,
                              void* d_out, int out_size)
{
    const float* particles = (const float*)d_in[0];
    const int*   senders   = (const int*)d_in[1];
    const int*   receivers = (const int*)d_in[2];
    const float* W1 = (const float*)d_in[3];
    const float* b1 = (const float*)d_in[4];
    const float* W2 = (const float*)d_in[5];
    const float* b2 = (const float*)d_in[6];
    const float* W3 = (const float*)d_in[7];
    const float* b3 = (const float*)d_in[8];
    const float* W4 = (const float*)d_in[9];
    const float* b4 = (const float*)d_in[10];
    float* out = (float*)d_out;

    node_proj_kernel<<<(BB * NN) / 256, 256>>>(particles, W1, b1);

    dim3 egrid(EE / 256, BB);
    edge_kernel<<<egrid, 256>>>(senders, receivers, W2, b2);

    node_out_kernel<<<(BB * NN) / 256, 256>>>(particles, W3, b3, W4, b4, out);
}